// round 9
// baseline (speedup 1.0000x reference)
#include <cuda_runtime.h>
#include <cuda_fp16.h>
#include <mma.h>
#include <cstdint>

using namespace nvcuda;

// v8: proven R2v2 scalar kernel (2400us) + in-band WMMA diagnostic.
// wmma_test runs the exact suspect fp16 hi/lo staging + WMMA code once,
// cross-checks against scalar references, and encodes failures as bits in
// g_bad; proj_kernel converts bits into deterministic ~1/2/4ms delays so
// the bench dur_us reports WHICH stage of the MMA path is broken.

#define TT   256
#define BB   256
#define KD   192
#define RH   256
#define BS   16
#define NG   16
#define GSTRIDE 18
#define SMEM_FLOATS (KD*RH + RH + RH*GSTRIDE)
#define SMEM_BYTES  (SMEM_FLOATS * 4)

__device__ float g_h[4][TT][BB][64];
__device__ float g_C[4][TT][BB][128];
__device__ float g_o[4][TT][BB][64];
__device__ int   g_hf[4][NG];
__device__ int   g_of[4][NG];
__device__ int   g_bad;
__device__ float g_sink;

__device__ __forceinline__ float sigm(float x){
    return __fdividef(1.f, 1.f + __expf(-x));
}
__device__ __forceinline__ float tanh_f(float x){
    float e = __expf(2.f * x);
    return 1.f - __fdividef(2.f, e + 1.f);
}
__device__ __forceinline__ void fma2(unsigned long long &acc,
                                     unsigned long long a, unsigned long long b){
    asm("fma.rn.f32x2 %0, %1, %2, %0;" : "+l"(acc) : "l"(a), "l"(b));
}
__device__ __forceinline__ unsigned long long dup2(float v){
    unsigned long long r; unsigned u = __float_as_uint(v);
    asm("mov.b64 %0, {%1, %1};" : "=l"(r) : "r"(u));
    return r;
}

extern "C" __global__ void reset_kernel(){
    int i = threadIdx.x;
    if (i < 4*NG){ ((int*)g_hf)[i] = 0; ((int*)g_of)[i] = 0; }
    if (i == 0) g_bad = 0;
}

// ============================ rnn (R2v2 verbatim, passed @2400us) ============
extern "C" __global__ void __launch_bounds__(256,1)
rnn_kernel(const float* __restrict__ X, const float* __restrict__ W,
           const float* __restrict__ Bv)
{
    extern __shared__ float sm[];
    float* sW = sm;
    float* sB = sm + KD*RH;
    float* sX = sB + RH;
    float* sG = sX;

    const int tid  = threadIdx.x;
    const int bid  = blockIdx.x;
    const int l    = bid >> 5;
    const int half = (bid >> 4) & 1;
    const int g    = bid & 15;
    const int G0   = g * BS;
    const int d    = (l==0) ? 1 : ((l==1) ? 3 : ((l==2) ? 6 : 12));

    const float* Wl = W + (size_t)l * 512 * KD;
    for (int idx = tid; idx < RH*KD; idx += 256){
        int r = idx / KD;
        int k = idx - r*KD;
        int grow = ((r>>6)<<7) + (half<<6) + (r&63);
        sW[k*RH + r] = Wl[(size_t)grow*KD + k];
    }
    {
        int grow = ((tid>>6)<<7) + (half<<6) + (tid&63);
        sB[tid] = Bv[l*512 + grow];
    }
    __syncthreads();

    const int rs = tid & 127;
    const int b0 = (tid >> 7) * 8;
    const int eb = tid & 15;
    const int s0 = (tid >> 4) << 2;

    float cP[4] = {0.f, 0.f, 0.f, 0.f};

    for (int t = 0; t < TT; ++t){
        if (tid == 0){
            if (l > 0){
                volatile int* fp = &g_of[l-1][g];
                while (*fp < t+1) {}
            }
            if (half == 0 && t > 0){
                volatile int* fp = &g_hf[l][g];
                while (*fp < t) {}
            }
            __threadfence();
        }
        __syncthreads();

        const float* srcX = (l==0) ? (X + ((size_t)t*BB + G0)*64)
                                   : &g_o[l-1][t][G0][0];
        const float* srcP = (t > 0)  ? &g_h[l][t-1][G0][0] : (const float*)0;
        const float* srcD = (t >= d) ? &g_h[l][t-d][G0][0] : srcP;
        #pragma unroll
        for (int it = 0; it < 12; ++it){
            int idx = it*256 + tid;
            int b   = idx & 15;
            int kk  = idx >> 4;
            int sec = kk >> 6;
            int c   = kk & 63;
            const float* s = (sec == 0) ? srcX : ((sec == 1) ? srcP : srcD);
            float v = s ? s[b*64 + c] : 0.f;
            sX[kk*16 + b] = v;
        }
        __syncthreads();

        unsigned long long a00=0,a01=0,a02=0,a03=0;
        unsigned long long a10=0,a11=0,a12=0,a13=0;
        const float* wp = sW + rs*2;
        const float* xp = sX + b0;
        #pragma unroll 4
        for (int k = 0; k < KD; ++k){
            float2 w = *(const float2*)(wp + (k<<8));
            unsigned long long w0 = dup2(w.x);
            unsigned long long w1 = dup2(w.y);
            const ulonglong2* xq = (const ulonglong2*)(xp + (k<<4));
            ulonglong2 xa = xq[0];
            ulonglong2 xb = xq[1];
            fma2(a00, w0, xa.x); fma2(a01, w0, xa.y);
            fma2(a02, w0, xb.x); fma2(a03, w0, xb.y);
            fma2(a10, w1, xa.x); fma2(a11, w1, xa.y);
            fma2(a12, w1, xb.x); fma2(a13, w1, xb.y);
        }
        __syncthreads();

        {
            unsigned long long* g0 = (unsigned long long*)(sG + (rs*2)*GSTRIDE + b0);
            unsigned long long* g1 = (unsigned long long*)(sG + (rs*2+1)*GSTRIDE + b0);
            g0[0]=a00; g0[1]=a01; g0[2]=a02; g0[3]=a03;
            g1[0]=a10; g1[1]=a11; g1[2]=a12; g1[3]=a13;
        }
        __syncthreads();

        float4 b0v = *(const float4*)(sB +         s0);
        float4 b1v = *(const float4*)(sB +  64  +  s0);
        float4 b2v = *(const float4*)(sB + 128  +  s0);
        float4 b3v = *(const float4*)(sB + 192  +  s0);
        float4 dC = make_float4(0.f, 0.f, 0.f, 0.f);
        if (t >= d) dC = *(const float4*)(&g_C[l][t-d][G0+eb][(half<<6) + s0]);

        float nc[4], wh[4];
        const float* dCp = &dC.x;
        const float* bp0 = &b0v.x; const float* bp1 = &b1v.x;
        const float* bp2 = &b2v.x; const float* bp3 = &b3v.x;
        #pragma unroll
        for (int i = 0; i < 4; ++i){
            int srow = s0 + i;
            float q0 = sG[(      srow)*GSTRIDE + eb];
            float q1 = sG[( 64 + srow)*GSTRIDE + eb];
            float q2 = sG[(128 + srow)*GSTRIDE + eb];
            float q3 = sG[(192 + srow)*GSTRIDE + eb];
            float f  = sigm(q0 + bp0[i] + 1.f);
            float ns = tanh_f(q1 + bp1[i]);
            float al = sigm(q2 + bp2[i]);
            float oo = sigm(q3 + bp3[i]);
            float wc = (t >= d) ? (al*cP[i] + (1.f-al)*dCp[i]) : cP[i];
            float c2 = (t > 0)  ? (f*wc + (1.f-f)*ns) : ns;
            nc[i] = c2; wh[i] = oo*c2; cP[i] = c2;
        }

        *(float4*)(&g_C[l][t][G0+eb][(half<<6) + s0]) =
            make_float4(nc[0], nc[1], nc[2], nc[3]);
        float* wdst = half ? &g_h[l][t][G0+eb][s0] : &g_o[l][t][G0+eb][s0];
        *(float4*)wdst = make_float4(wh[0], wh[1], wh[2], wh[3]);

        __threadfence();
        __syncthreads();
        if (tid == 0){
            if (half) *(volatile int*)&g_hf[l][g] = t + 1;
            else      *(volatile int*)&g_of[l][g] = t + 1;
        }
    }
}

// ============================ wmma diagnostic =================================
// Exact R7 staging + WMMA code on W[0] rows 0..127 and X-derived B.
// bit0: A hi/lo staging wrong   bit1: B hi/lo staging wrong
// bit2: WMMA result != scalar on the same dequantized data
#define T_AST 200
#define T_BST 200
#define T_GST 20
#define TS_AHI 0
#define TS_ALO (TS_AHI + 128*T_AST*2)     // 51200
#define TS_BHI (TS_ALO + 128*T_AST*2)     // 102400
#define TS_BLO (TS_BHI + 16*T_BST*2)      // 108800
#define TS_G   (TS_BLO + 16*T_BST*2)      // 115200
#define TS_TOTAL (TS_G + 128*T_GST*4)     // 125440

extern "C" __global__ void __launch_bounds__(256,1)
wmma_test(const float* __restrict__ X, const float* __restrict__ W)
{
    extern __shared__ char smem[];
    __half* sAhi = (__half*)(smem + TS_AHI);
    __half* sAlo = (__half*)(smem + TS_ALO);
    __half* sBhi = (__half*)(smem + TS_BHI);
    __half* sBlo = (__half*)(smem + TS_BLO);
    float*  sG   = (float*)(smem + TS_G);
    const int tid = threadIdx.x;
    const int wid = tid >> 5;
    const float sc = 2.44140625e-4f;   // 2^-12

    // ---- A staging: EXACT R7 weight-loop structure (128 rows, grow = r) ----
    #pragma unroll 4
    for (int it = 0; it < 48; ++it){
        int idx = it*512 + tid*2;
        int r = idx / KD;
        int k = idx - r*KD;
        float2 w = *(const float2*)(W + (size_t)r*KD + k);
        __half hx = __float2half_rn(w.x);
        __half hy = __float2half_rn(w.y);
        float lx = (w.x - __half2float(hx)) * 4096.f;
        float ly = (w.y - __half2float(hy)) * 4096.f;
        *(__half2*)(sAhi + r*T_AST + k) = __halves2half2(hx, hy);
        *(__half2*)(sAlo + r*T_AST + k) =
            __halves2half2(__float2half_rn(lx), __float2half_rn(ly));
    }

    // ---- B staging: EXACT R7 x-staging structure, real data in all sections --
    const float* srcX = X;             // batches 0..15, cols 0..63
    const float* srcP = X + 16*64;     // stand-in prevH
    const float* srcD = X + 32*64;     // stand-in dH
    #pragma unroll
    for (int it = 0; it < 6; ++it){
        int idx = it*512 + tid*2;
        int sec = idx >> 10;
        int rem = idx & 1023;
        int b   = rem >> 6;
        int c   = rem & 63;
        const float* s = (sec == 0) ? srcX : ((sec == 1) ? srcP : srcD);
        float2 v = *(const float2*)(s + b*64 + c);
        __half hx = __float2half_rn(v.x);
        __half hy = __float2half_rn(v.y);
        float lx = (v.x - __half2float(hx)) * 4096.f;
        float ly = (v.y - __half2float(hy)) * 4096.f;
        int k = sec*64 + c;
        *(__half2*)(sBhi + b*T_BST + k) = __halves2half2(hx, hy);
        *(__half2*)(sBlo + b*T_BST + k) =
            __halves2half2(__float2half_rn(lx), __float2half_rn(ly));
    }
    __syncthreads();

    // ---- check bit0: dequant(A) vs global W ----
    for (int i = tid; i < 128*KD; i += 256){
        int r = i / KD, k = i - (i/KD)*KD;
        float w = W[(size_t)r*KD + k];
        float dq = __half2float(sAhi[r*T_AST + k])
                 + __half2float(sAlo[r*T_AST + k]) * sc;
        if (fabsf(dq - w) > 1e-5f*(1.f + fabsf(w))) atomicOr(&g_bad, 1);
    }
    // ---- check bit1: dequant(B) vs source ----
    for (int i = tid; i < 16*KD; i += 256){
        int b = i / KD, k = i - (i/KD)*KD;
        int sec = k >> 6, c = k & 63;
        const float* s = (sec == 0) ? srcX : ((sec == 1) ? srcP : srcD);
        float xv = s[b*64 + c];
        float dq = __half2float(sBhi[b*T_BST + k])
                 + __half2float(sBlo[b*T_BST + k]) * sc;
        if (fabsf(dq - xv) > 1e-5f*(1.f + fabsf(xv))) atomicOr(&g_bad, 2);
    }
    __syncthreads();

    // ---- WMMA: EXACT R7 mainloop structure (8 warps x one 16-row m-tile) ----
    {
        const int m0 = wid * 16;
        wmma::fragment<wmma::accumulator, 16,16,16, float> accH, accL;
        wmma::fill_fragment(accH, 0.f);
        wmma::fill_fragment(accL, 0.f);
        #pragma unroll 2
        for (int kt = 0; kt < 12; ++kt){
            int k0 = kt * 16;
            wmma::fragment<wmma::matrix_b, 16,16,16, __half, wmma::col_major> bH, bL;
            wmma::load_matrix_sync(bH, sBhi + k0, T_BST);
            wmma::load_matrix_sync(bL, sBlo + k0, T_BST);
            wmma::fragment<wmma::matrix_a, 16,16,16, __half, wmma::row_major> aH, aL;
            wmma::load_matrix_sync(aH, sAhi + m0*T_AST + k0, T_AST);
            wmma::load_matrix_sync(aL, sAlo + m0*T_AST + k0, T_AST);
            wmma::mma_sync(accH, aH, bH, accH);
            wmma::mma_sync(accL, aH, bL, accL);
            wmma::mma_sync(accL, aL, bH, accL);
        }
        #pragma unroll
        for (int i = 0; i < accH.num_elements; ++i)
            accH.x[i] = fmaf(accL.x[i], sc, accH.x[i]);
        wmma::store_matrix_sync(sG + m0*T_GST, accH, T_GST, wmma::mem_row_major);
    }
    __syncthreads();

    // ---- check bit2: WMMA gates vs scalar on the SAME dequantized data ----
    {
        int r  = tid & 127;
        int n0 = (tid >> 7) * 8;
        for (int n = n0; n < n0 + 8; ++n){
            float s = 0.f;
            for (int k = 0; k < KD; ++k){
                float av = __half2float(sAhi[r*T_AST + k])
                         + __half2float(sAlo[r*T_AST + k]) * sc;
                float bv = __half2float(sBhi[n*T_BST + k])
                         + __half2float(sBlo[n*T_BST + k]) * sc;
                s = fmaf(av, bv, s);
            }
            float gv = sG[r*T_GST + n];
            if (fabsf(gv - s) > 1e-3f*(1.f + fabsf(s))) atomicOr(&g_bad, 4);
        }
    }
    __threadfence();
}

// ============================ projection + delay readout =====================
extern "C" __global__ void __launch_bounds__(256)
proj_kernel(const float* __restrict__ Wa, const float* __restrict__ ba,
            float* __restrict__ out)
{
    __shared__ float sWa[64*64];
    __shared__ float sba[64];
    for (int i = threadIdx.x; i < 4096; i += 256) sWa[i] = Wa[i];
    if (threadIdx.x < 64) sba[threadIdx.x] = ba[threadIdx.x];
    __syncthreads();

    int row = blockIdx.x * 256 + threadIdx.x;
    const float* p1 = &g_o[1][0][0][0] + (size_t)row * 64;
    const float* p3 = &g_o[3][0][0][0] + (size_t)row * 64;
    float v[64];
    #pragma unroll
    for (int i = 0; i < 64; i += 4){
        float4 a = *(const float4*)(p1 + i);
        float4 c = *(const float4*)(p3 + i);
        v[i+0] = a.x + c.x;  v[i+1] = a.y + c.y;
        v[i+2] = a.z + c.z;  v[i+3] = a.w + c.w;
    }
    float* orow = out + (size_t)row * 64;
    for (int j = 0; j < 64; ++j){
        float acc = sba[j];
        const float* wr = sWa + j*64;
        #pragma unroll
        for (int i = 0; i < 64; ++i) acc = fmaf(v[i], wr[i], acc);
        orow[j] = acc;
    }

    // ---- diagnostic delay: dur_us encodes g_bad (deterministic per input) ----
    if (blockIdx.x == 0 && threadIdx.x == 0){
        int bad = *(volatile int*)&g_bad;
        long long iters = 0;
        if (bad & 1) iters +=  500000;   // ~1.0ms : A staging wrong
        if (bad & 2) iters += 1000000;   // ~2.1ms : B staging wrong
        if (bad & 4) iters += 2000000;   // ~4.2ms : WMMA fragment path wrong
        float acc = 1.000001f;
        for (long long i = 0; i < iters; ++i)
            acc = fmaf(acc, 1.0000001f, 1e-7f);
        if (acc == 0.f) g_sink = acc;    // unreachable; prevents DCE
    }
}

extern "C" void kernel_launch(void* const* d_in, const int* in_sizes, int n_in,
                              void* d_out, int out_size)
{
    const float* x  = (const float*)d_in[0];
    const float* W  = (const float*)d_in[1];
    const float* b  = (const float*)d_in[2];
    const float* Wa = (const float*)d_in[3];
    const float* ba = (const float*)d_in[4];

    cudaFuncSetAttribute((const void*)rnn_kernel,
                         cudaFuncAttributeMaxDynamicSharedMemorySize, SMEM_BYTES);
    cudaFuncSetAttribute((const void*)wmma_test,
                         cudaFuncAttributeMaxDynamicSharedMemorySize, TS_TOTAL);

    // 4 launches/call: ncu -s 5 lands on call2's rnn_kernel.
    reset_kernel<<<1, 64>>>();
    rnn_kernel<<<128, 256, SMEM_BYTES>>>(x, W, b);
    wmma_test<<<1, 256, TS_TOTAL>>>(x, W);
    proj_kernel<<<256, 256>>>(Wa, ba, (float*)d_out);
}